// round 6
// baseline (speedup 1.0000x reference)
#include <cuda_runtime.h>
#include <math.h>

#define B_ 2
#define S_ 2048
#define H_ 16
#define D_ 64
#define E_ 1024
#define M_ (B_*S_)

// Scratch (allocation-free)
__device__ float g_q[B_*H_*S_*D_];
__device__ float g_k[B_*H_*S_*D_];
__device__ float g_v[B_*H_*S_*D_];
__device__ float g_attn[(size_t)B_*S_*E_];
__device__ float g_cos[S_*D_];
__device__ float g_sin[S_*D_];

// ---------------------------------------------------------------------------
__device__ __forceinline__ unsigned f2tf(float x) {
    unsigned r;
    asm("cvt.rna.tf32.f32 %0, %1;" : "=r"(r) : "f"(x));
    return r;
}

__device__ __forceinline__ void mma_tf32(float c[4], const unsigned a[4], const unsigned b[2]) {
    asm volatile(
        "mma.sync.aligned.m16n8k8.row.col.f32.tf32.tf32.f32 "
        "{%0,%1,%2,%3},{%4,%5,%6,%7},{%8,%9},{%0,%1,%2,%3};\n"
        : "+f"(c[0]), "+f"(c[1]), "+f"(c[2]), "+f"(c[3])
        : "r"(a[0]), "r"(a[1]), "r"(a[2]), "r"(a[3]), "r"(b[0]), "r"(b[1]));
}

// ---------------------------------------------------------------------------
__global__ void rope_table_kernel() {
    int idx = blockIdx.x * blockDim.x + threadIdx.x;
    if (idx >= S_ * D_) return;
    int sp = idx >> 6, d = idx & 63;
    float e = (float)(2 * (d & 31)) * (1.0f / 64.0f);
    float inv = powf(10000.0f, -e);
    float s, c;
    sincosf((float)sp * inv, &s, &c);
    g_cos[idx] = c;
    g_sin[idx] = s;
}

// ---------------------------------------------------------------------------
// tf32 TC GEMM body, double-buffered. C[m,n] = sum_k A[m,k]*W[n,k] + bias[n].
// MODE 0: plain -> out[m*E+n]
// MODE 1: RoPE  -> [B,H,S,D]
// MODE 2: plain -> [B,H,S,D]
// 128x128x32 tile, 256 threads (8 warps), warp tile 32x64.
// ---------------------------------------------------------------------------
template<int MODE>
__device__ __forceinline__ void gemm_body(
    const float* __restrict__ A, const float* __restrict__ W,
    const float* __restrict__ bias, float* __restrict__ out,
    int m0, int n0, unsigned* smg)
{
    unsigned (*As)[36] = (unsigned(*)[36])smg;
    unsigned (*Bs)[36] = (unsigned(*)[36])(smg + 2*128*36);

    const int tid = threadIdx.x;
    const int lane = tid & 31, wid = tid >> 5;
    const int warp_m = wid >> 1, warp_n = wid & 1;
    const int lq = lane >> 2, lr = lane & 3;
    const int l_row = tid >> 3;
    const int l_f   = (tid & 7) * 4;

    float c[2][8][4];
    #pragma unroll
    for (int mt = 0; mt < 2; mt++)
        #pragma unroll
        for (int nt = 0; nt < 8; nt++)
            #pragma unroll
            for (int i = 0; i < 4; i++) c[mt][nt][i] = 0.f;

    float4 pa[4], pb[4];
    #pragma unroll
    for (int it = 0; it < 4; it++) {
        int row = l_row + it * 32;
        pa[it] = *(const float4*)(A + (size_t)(m0 + row) * E_ + l_f);
        pb[it] = *(const float4*)(W + (size_t)(n0 + row) * E_ + l_f);
    }
    #pragma unroll
    for (int it = 0; it < 4; it++) {
        int row = l_row + it * 32;
        uint4 u; u.x = f2tf(pa[it].x); u.y = f2tf(pa[it].y); u.z = f2tf(pa[it].z); u.w = f2tf(pa[it].w);
        *(uint4*)&As[row][l_f] = u;
        uint4 v; v.x = f2tf(pb[it].x); v.y = f2tf(pb[it].y); v.z = f2tf(pb[it].z); v.w = f2tf(pb[it].w);
        *(uint4*)&Bs[row][l_f] = v;
    }
    __syncthreads();

    const int NKT = E_ / 32;
    for (int kt = 0; kt < NKT; kt++) {
        const int cur = (kt & 1) * 128;
        if (kt + 1 < NKT) {
            int k0 = (kt + 1) * 32;
            #pragma unroll
            for (int it = 0; it < 4; it++) {
                int row = l_row + it * 32;
                pa[it] = *(const float4*)(A + (size_t)(m0 + row) * E_ + k0 + l_f);
                pb[it] = *(const float4*)(W + (size_t)(n0 + row) * E_ + k0 + l_f);
            }
        }
        #pragma unroll
        for (int kk = 0; kk < 4; kk++) {
            int koff = kk * 8;
            unsigned bfr[8][2];
            #pragma unroll
            for (int nt = 0; nt < 8; nt++) {
                int nc = cur + warp_n * 64 + nt * 8 + lq;
                bfr[nt][0] = Bs[nc][koff + lr];
                bfr[nt][1] = Bs[nc][koff + 4 + lr];
            }
            unsigned afr[2][4];
            #pragma unroll
            for (int mt = 0; mt < 2; mt++) {
                int mr = cur + warp_m * 32 + mt * 16 + lq;
                afr[mt][0] = As[mr][koff + lr];
                afr[mt][1] = As[mr + 8][koff + lr];
                afr[mt][2] = As[mr][koff + 4 + lr];
                afr[mt][3] = As[mr + 8][koff + 4 + lr];
            }
            #pragma unroll
            for (int mt = 0; mt < 2; mt++)
                #pragma unroll
                for (int nt = 0; nt < 8; nt++)
                    mma_tf32(c[mt][nt], afr[mt], bfr[nt]);
        }
        if (kt + 1 < NKT) {
            const int nxt = ((kt + 1) & 1) * 128;
            #pragma unroll
            for (int it = 0; it < 4; it++) {
                int row = nxt + l_row + it * 32;
                uint4 u; u.x = f2tf(pa[it].x); u.y = f2tf(pa[it].y); u.z = f2tf(pa[it].z); u.w = f2tf(pa[it].w);
                *(uint4*)&As[row][l_f] = u;
                uint4 v; v.x = f2tf(pb[it].x); v.y = f2tf(pb[it].y); v.z = f2tf(pb[it].z); v.w = f2tf(pb[it].w);
                *(uint4*)&Bs[row][l_f] = v;
            }
            __syncthreads();
        }
    }

    // epilogue
    #pragma unroll
    for (int mt = 0; mt < 2; mt++) {
        #pragma unroll
        for (int rh = 0; rh < 2; rh++) {
            int m = m0 + warp_m * 32 + mt * 16 + lq + rh * 8;
            int bb = m >> 11, sp = m & (S_ - 1);
            #pragma unroll
            for (int nt = 0; nt < 8; nt++) {
                int n = n0 + warp_n * 64 + nt * 8 + lr * 2;
                float2 b2 = *(const float2*)(bias + n);
                float v0 = c[mt][nt][rh * 2]     + b2.x;
                float v1 = c[mt][nt][rh * 2 + 1] + b2.y;
                if (MODE == 0) {
                    *(float2*)(out + (size_t)m * E_ + n) = make_float2(v0, v1);
                } else {
                    int h = n >> 6, d = n & 63;
                    float o0 = v0, o1 = v1;
                    if (MODE == 1) {
                        float2 cs = *(const float2*)(g_cos + sp * D_ + d);
                        float2 sn = *(const float2*)(g_sin + sp * D_ + d);
                        o0 = v0 * cs.x - v1 * sn.x;
                        o1 = v1 * cs.y + v0 * sn.y;
                    }
                    size_t base = (((size_t)(bb * H_ + h)) * S_ + sp) * D_ + d;
                    *(float2*)(out + base) = make_float2(o0, o1);
                }
            }
        }
    }
}

// ---------------------------------------------------------------------------
// Fused QKV projection: grid.z selects Q(0)/K(1)/V(2). RoPE on Q,K.
// ---------------------------------------------------------------------------
__global__ __launch_bounds__(256) void qkv_tc(
    const float* __restrict__ x,
    const float* __restrict__ Wq, const float* __restrict__ bq,
    const float* __restrict__ Wk, const float* __restrict__ bk,
    const float* __restrict__ Wv, const float* __restrict__ bv)
{
    extern __shared__ unsigned smg[];
    const int z = blockIdx.z;
    const int m0 = blockIdx.y * 128, n0 = blockIdx.x * 128;
    if (z == 0) {
        gemm_body<1>(x, Wq, bq, g_q, m0, n0, smg);
    } else if (z == 1) {
        gemm_body<1>(x, Wk, bk, g_k, m0, n0, smg);
    } else {
        gemm_body<2>(x, Wv, bv, g_v, m0, n0, smg);
    }
}

// ---------------------------------------------------------------------------
// Output projection
// ---------------------------------------------------------------------------
__global__ __launch_bounds__(256) void out_tc(
    const float* __restrict__ A, const float* __restrict__ W,
    const float* __restrict__ bias, float* __restrict__ out)
{
    extern __shared__ unsigned smg[];
    gemm_body<0>(A, W, bias, out, blockIdx.y * 128, blockIdx.x * 128, smg);
}

// ---------------------------------------------------------------------------
// Flash attention, tf32 mma. 256 threads (8 warps), Q tile 128 rows,
// K/V tile 64 with register prefetch. Q frags in regs (pre-scaled 1/8).
// ---------------------------------------------------------------------------
__global__ __launch_bounds__(256) void attn_tc(float* __restrict__ outbuf)
{
    extern __shared__ unsigned smu[];
    unsigned (*Ks)[68] = (unsigned(*)[68])smu;               // 64 x 68
    unsigned (*Vs)[68] = (unsigned(*)[68])(smu + 64*68);     // 64 x 68
    unsigned (*Ps)[68] = (unsigned(*)[68])(smu + 2*64*68);   // 128 x 68 (also Q staging)

    const int tid = threadIdx.x;
    const int lane = tid & 31, wid = tid >> 5;
    const int lq = lane >> 2, lr = lane & 3;
    const int wr = wid * 16;
    const int q0 = blockIdx.x * 128;
    const int h = blockIdx.y, bb = blockIdx.z;
    const size_t head_base = ((size_t)(bb * H_ + h)) * S_ * D_;

    // stage Q tile (128x64, scaled by 1/8) into Ps, extract fragments
    #pragma unroll
    for (int it = 0; it < 8; it++) {
        int id = tid + it * 256;
        int row = id >> 4, f = (id & 15) * 4;
        float4 v = *(const float4*)(g_q + head_base + (size_t)(q0 + row) * D_ + f);
        uint4 u;
        u.x = f2tf(v.x * 0.125f); u.y = f2tf(v.y * 0.125f);
        u.z = f2tf(v.z * 0.125f); u.w = f2tf(v.w * 0.125f);
        *(uint4*)&Ps[row][f] = u;
    }
    __syncthreads();

    unsigned qfr[8][4];
    #pragma unroll
    for (int kk = 0; kk < 8; kk++) {
        int koff = kk * 8;
        qfr[kk][0] = Ps[wr + lq][koff + lr];
        qfr[kk][1] = Ps[wr + lq + 8][koff + lr];
        qfr[kk][2] = Ps[wr + lq][koff + 4 + lr];
        qfr[kk][3] = Ps[wr + lq + 8][koff + 4 + lr];
    }
    __syncthreads();   // everyone done reading Q staging before Ps reuse

    float o[8][4];
    float m_i[2] = {-1e30f, -1e30f}, l_i[2] = {0.f, 0.f};
    #pragma unroll
    for (int nt = 0; nt < 8; nt++)
        #pragma unroll
        for (int i = 0; i < 4; i++) o[nt][i] = 0.f;

    float4 pk4[4], pv4[4];

    // prologue: load K/V tile 0 into regs, store to smem
    #pragma unroll
    for (int it = 0; it < 4; it++) {
        int id = tid + it * 256;
        int row = id >> 4, f = (id & 15) * 4;
        pk4[it] = *(const float4*)(g_k + head_base + (size_t)row * D_ + f);
        pv4[it] = *(const float4*)(g_v + head_base + (size_t)row * D_ + f);
    }
    #pragma unroll
    for (int it = 0; it < 4; it++) {
        int id = tid + it * 256;
        int row = id >> 4, f = (id & 15) * 4;
        uint4 u; u.x = f2tf(pk4[it].x); u.y = f2tf(pk4[it].y); u.z = f2tf(pk4[it].z); u.w = f2tf(pk4[it].w);
        *(uint4*)&Ks[row][f] = u;
        uint4 w; w.x = f2tf(pv4[it].x); w.y = f2tf(pv4[it].y); w.z = f2tf(pv4[it].z); w.w = f2tf(pv4[it].w);
        *(uint4*)&Vs[row][f] = w;
    }
    __syncthreads();

    const int NT = S_ / 64;   // 32
    for (int kt = 0; kt < NT; kt++) {
        // prefetch next K/V tile into registers
        if (kt + 1 < NT) {
            size_t nb = head_base + (size_t)(kt + 1) * 64 * D_;
            #pragma unroll
            for (int it = 0; it < 4; it++) {
                int id = tid + it * 256;
                int row = id >> 4, f = (id & 15) * 4;
                pk4[it] = *(const float4*)(g_k + nb + (size_t)row * D_ + f);
                pv4[it] = *(const float4*)(g_v + nb + (size_t)row * D_ + f);
            }
        }

        // S = (Q/8) K^T
        float s[8][4];
        #pragma unroll
        for (int nt = 0; nt < 8; nt++)
            #pragma unroll
            for (int i = 0; i < 4; i++) s[nt][i] = 0.f;

        #pragma unroll
        for (int kk = 0; kk < 8; kk++) {
            int koff = kk * 8;
            #pragma unroll
            for (int nt = 0; nt < 8; nt++) {
                unsigned bfr[2];
                bfr[0] = Ks[nt * 8 + lq][koff + lr];
                bfr[1] = Ks[nt * 8 + lq][koff + 4 + lr];
                mma_tf32(s[nt], qfr[kk], bfr);
            }
        }

        // online softmax
        #pragma unroll
        for (int rh = 0; rh < 2; rh++) {
            float mx = -1e30f;
            #pragma unroll
            for (int nt = 0; nt < 8; nt++)
                mx = fmaxf(mx, fmaxf(s[nt][rh*2], s[nt][rh*2+1]));
            mx = fmaxf(mx, __shfl_xor_sync(0xffffffffu, mx, 1));
            mx = fmaxf(mx, __shfl_xor_sync(0xffffffffu, mx, 2));
            float mnew = fmaxf(m_i[rh], mx);
            float corr = __expf(m_i[rh] - mnew);
            m_i[rh] = mnew;
            float sum = 0.f;
            #pragma unroll
            for (int nt = 0; nt < 8; nt++) {
                float p0 = __expf(s[nt][rh*2]   - mnew);
                float p1 = __expf(s[nt][rh*2+1] - mnew);
                s[nt][rh*2] = p0; s[nt][rh*2+1] = p1;
                sum += p0 + p1;
            }
            sum += __shfl_xor_sync(0xffffffffu, sum, 1);
            sum += __shfl_xor_sync(0xffffffffu, sum, 2);
            l_i[rh] = l_i[rh] * corr + sum;
            #pragma unroll
            for (int nt = 0; nt < 8; nt++) {
                o[nt][rh*2]   *= corr;
                o[nt][rh*2+1] *= corr;
            }
        }

        // P -> smem (warp-private rows)
        #pragma unroll
        for (int nt = 0; nt < 8; nt++) {
            int col = nt * 8 + lr * 2;
            *(uint2*)&Ps[wr + lq][col]     = make_uint2(f2tf(s[nt][0]), f2tf(s[nt][1]));
            *(uint2*)&Ps[wr + lq + 8][col] = make_uint2(f2tf(s[nt][2]), f2tf(s[nt][3]));
        }
        __syncwarp();

        // O += P V
        #pragma unroll
        for (int kk = 0; kk < 8; kk++) {
            int koff = kk * 8;
            unsigned afr[4];
            afr[0] = Ps[wr + lq][koff + lr];
            afr[1] = Ps[wr + lq + 8][koff + lr];
            afr[2] = Ps[wr + lq][koff + 4 + lr];
            afr[3] = Ps[wr + lq + 8][koff + 4 + lr];
            #pragma unroll
            for (int nt = 0; nt < 8; nt++) {
                unsigned bfr[2];
                bfr[0] = Vs[koff + lr][nt * 8 + lq];
                bfr[1] = Vs[koff + 4 + lr][nt * 8 + lq];
                mma_tf32(o[nt], afr, bfr);
            }
        }

        // stage prefetched tile
        if (kt + 1 < NT) {
            __syncthreads();   // all warps done reading Ks/Vs
            #pragma unroll
            for (int it = 0; it < 4; it++) {
                int id = tid + it * 256;
                int row = id >> 4, f = (id & 15) * 4;
                uint4 u; u.x = f2tf(pk4[it].x); u.y = f2tf(pk4[it].y); u.z = f2tf(pk4[it].z); u.w = f2tf(pk4[it].w);
                *(uint4*)&Ks[row][f] = u;
                uint4 w; w.x = f2tf(pv4[it].x); w.y = f2tf(pv4[it].y); w.z = f2tf(pv4[it].z); w.w = f2tf(pv4[it].w);
                *(uint4*)&Vs[row][f] = w;
            }
            __syncthreads();
        }
    }

    // normalize + write [B,S,H,D]
    float inv0 = 1.0f / l_i[0], inv1 = 1.0f / l_i[1];
    #pragma unroll
    for (int nt = 0; nt < 8; nt++) {
        int d = nt * 8 + lr * 2;
        size_t i0 = (((size_t)bb * S_ + q0 + wr + lq) * H_ + h) * D_ + d;
        size_t i1 = (((size_t)bb * S_ + q0 + wr + lq + 8) * H_ + h) * D_ + d;
        *(float2*)(outbuf + i0) = make_float2(o[nt][0] * inv0, o[nt][1] * inv0);
        *(float2*)(outbuf + i1) = make_float2(o[nt][2] * inv1, o[nt][3] * inv1);
    }
}

// ---------------------------------------------------------------------------
extern "C" void kernel_launch(void* const* d_in, const int* in_sizes, int n_in,
                              void* d_out, int out_size)
{
    const float* x  = (const float*)d_in[0];
    const float* Wq = (const float*)d_in[1];
    const float* bq = (const float*)d_in[2];
    const float* Wk = (const float*)d_in[3];
    const float* bk = (const float*)d_in[4];
    const float* Wv = (const float*)d_in[5];
    const float* bv = (const float*)d_in[6];
    const float* Wo = (const float*)d_in[7];
    const float* bo = (const float*)d_in[8];
    float* out = (float*)d_out;

    float *pa;
    cudaGetSymbolAddress((void**)&pa, g_attn);

    const int smem_gemm = 2 * 2 * 128 * 36 * sizeof(unsigned);      // 73728
    const int smem_attn = (64 + 64 + 128) * 68 * sizeof(unsigned);  // 69632
    cudaFuncSetAttribute(qkv_tc, cudaFuncAttributeMaxDynamicSharedMemorySize, smem_gemm);
    cudaFuncSetAttribute(out_tc, cudaFuncAttributeMaxDynamicSharedMemorySize, smem_gemm);
    cudaFuncSetAttribute(attn_tc, cudaFuncAttributeMaxDynamicSharedMemorySize, smem_attn);

    rope_table_kernel<<<(S_*D_ + 255)/256, 256>>>();

    qkv_tc<<<dim3(E_/128, M_/128, 3), 256, smem_gemm>>>(x, Wq, bq, Wk, bk, Wv, bv);
    attn_tc<<<dim3(S_/128, H_, B_), 256, smem_attn>>>(pa);
    out_tc<<<dim3(E_/128, M_/128), 256, smem_gemm>>>(pa, Wo, bo, out);
}

// round 9
// speedup vs baseline: 1.1209x; 1.1209x over previous
#include <cuda_runtime.h>
#include <math.h>

#define B_ 2
#define S_ 2048
#define H_ 16
#define D_ 64
#define E_ 1024
#define M_ (B_*S_)

// Scratch (allocation-free)
__device__ float g_q[B_*H_*S_*D_];
__device__ float g_k[B_*H_*S_*D_];
__device__ float g_v[B_*H_*S_*D_];
__device__ float g_attn[(size_t)B_*S_*E_];
__device__ float g_cos[S_*D_];
__device__ float g_sin[S_*D_];

// ---------------------------------------------------------------------------
__device__ __forceinline__ unsigned f2tf(float x) {
    unsigned r;
    asm("cvt.rna.tf32.f32 %0, %1;" : "=r"(r) : "f"(x));
    return r;
}

__device__ __forceinline__ void mma_tf32(float c[4], const unsigned a[4], const unsigned b[2]) {
    asm volatile(
        "mma.sync.aligned.m16n8k8.row.col.f32.tf32.tf32.f32 "
        "{%0,%1,%2,%3},{%4,%5,%6,%7},{%8,%9},{%0,%1,%2,%3};\n"
        : "+f"(c[0]), "+f"(c[1]), "+f"(c[2]), "+f"(c[3])
        : "r"(a[0]), "r"(a[1]), "r"(a[2]), "r"(a[3]), "r"(b[0]), "r"(b[1]));
}

// ldmatrix x4: loads 4 8x8-b16 matrices (= 4 8x4-tf32 tiles); per-lane row ptrs
__device__ __forceinline__ void ldsm4(unsigned &r0, unsigned &r1, unsigned &r2, unsigned &r3,
                                      unsigned addr) {
    asm volatile("ldmatrix.sync.aligned.m8n8.x4.shared.b16 {%0,%1,%2,%3}, [%4];"
                 : "=r"(r0), "=r"(r1), "=r"(r2), "=r"(r3) : "r"(addr));
}

__device__ __forceinline__ unsigned smem_u32(const void* p) {
    return (unsigned)__cvta_generic_to_shared(p);
}

// ---------------------------------------------------------------------------
__global__ void rope_table_kernel() {
    int idx = blockIdx.x * blockDim.x + threadIdx.x;
    if (idx >= S_ * D_) return;
    int sp = idx >> 6, d = idx & 63;
    float e = (float)(2 * (d & 31)) * (1.0f / 64.0f);
    float inv = powf(10000.0f, -e);
    float s, c;
    sincosf((float)sp * inv, &s, &c);
    g_cos[idx] = c;
    g_sin[idx] = s;
}

// ---------------------------------------------------------------------------
// tf32 TC GEMM, double-buffered, ldmatrix fragments.
// C[m,n] = sum_k A[m,k]*W[n,k] + bias[n]
// MODE 0: plain -> out[m*E+n]; MODE 1: RoPE -> [B,H,S,D]; MODE 2: -> [B,H,S,D]
// 128x128x32 tile, 256 threads (8 warps), warp tile 32x64.
// ---------------------------------------------------------------------------
template<int MODE>
__global__ __launch_bounds__(256) void gemm_tc(
    const float* __restrict__ A, const float* __restrict__ W,
    const float* __restrict__ bias, float* __restrict__ out)
{
    extern __shared__ unsigned smg[];
    unsigned (*As)[36] = (unsigned(*)[36])smg;              // [2*128][36]
    unsigned (*Bs)[36] = (unsigned(*)[36])(smg + 2*128*36); // [2*128][36]

    const int tid = threadIdx.x;
    const int lane = tid & 31, wid = tid >> 5;
    const int warp_m = wid >> 1, warp_n = wid & 1;
    const int m0 = blockIdx.y * 128, n0 = blockIdx.x * 128;
    const int lq = lane >> 2, lr = lane & 3;

    // ldmatrix per-lane offsets
    const int a_ro = (lane & 7) + ((lane >> 3) & 1) * 8;   // row  (matrix pair in m)
    const int a_co = ((lane >> 4) & 1) * 4;                // col  (k half)
    const int b_ro = (lane & 7) + ((lane >> 4) & 1) * 8;   // row  (n), matrices 2,3 = +8
    const int b_co = ((lane >> 3) & 1) * 4;                // col  (k half), matrices 1,3

    const unsigned as_u = smem_u32(&As[0][0]);
    const unsigned bs_u = smem_u32(&Bs[0][0]);

    const int l_row = tid >> 3;
    const int l_f   = (tid & 7) * 4;

    float c[2][8][4];
    #pragma unroll
    for (int mt = 0; mt < 2; mt++)
        #pragma unroll
        for (int nt = 0; nt < 8; nt++)
            #pragma unroll
            for (int i = 0; i < 4; i++) c[mt][nt][i] = 0.f;

    float4 pa[4], pb[4];
    #pragma unroll
    for (int it = 0; it < 4; it++) {
        int row = l_row + it * 32;
        pa[it] = *(const float4*)(A + (size_t)(m0 + row) * E_ + l_f);
        pb[it] = *(const float4*)(W + (size_t)(n0 + row) * E_ + l_f);
    }
    #pragma unroll
    for (int it = 0; it < 4; it++) {
        int row = l_row + it * 32;
        uint4 u; u.x = f2tf(pa[it].x); u.y = f2tf(pa[it].y); u.z = f2tf(pa[it].z); u.w = f2tf(pa[it].w);
        *(uint4*)&As[row][l_f] = u;
        uint4 v; v.x = f2tf(pb[it].x); v.y = f2tf(pb[it].y); v.z = f2tf(pb[it].z); v.w = f2tf(pb[it].w);
        *(uint4*)&Bs[row][l_f] = v;
    }
    __syncthreads();

    const int NKT = E_ / 32;
    for (int kt = 0; kt < NKT; kt++) {
        const int cur = (kt & 1) * 128;
        if (kt + 1 < NKT) {
            int k0 = (kt + 1) * 32;
            #pragma unroll
            for (int it = 0; it < 4; it++) {
                int row = l_row + it * 32;
                pa[it] = *(const float4*)(A + (size_t)(m0 + row) * E_ + k0 + l_f);
                pb[it] = *(const float4*)(W + (size_t)(n0 + row) * E_ + k0 + l_f);
            }
        }
        // base shared addrs for this buffer
        const unsigned a_base = as_u + (((cur + warp_m * 32 + a_ro) * 36) + a_co) * 4u;
        const unsigned b_base = bs_u + (((cur + warp_n * 64 + b_ro) * 36) + b_co) * 4u;
        #pragma unroll
        for (int kk = 0; kk < 4; kk++) {
            int koff = kk * 8;
            unsigned afr[2][4];
            #pragma unroll
            for (int mt = 0; mt < 2; mt++)
                ldsm4(afr[mt][0], afr[mt][1], afr[mt][2], afr[mt][3],
                      a_base + (mt * 16 * 36 + koff) * 4u);
            unsigned bfr[8][2];
            #pragma unroll
            for (int p = 0; p < 4; p++) {
                unsigned r0, r1, r2, r3;
                ldsm4(r0, r1, r2, r3, b_base + (p * 16 * 36 + koff) * 4u);
                bfr[2*p][0] = r0; bfr[2*p][1] = r1;
                bfr[2*p+1][0] = r2; bfr[2*p+1][1] = r3;
            }
            #pragma unroll
            for (int mt = 0; mt < 2; mt++)
                #pragma unroll
                for (int nt = 0; nt < 8; nt++)
                    mma_tf32(c[mt][nt], afr[mt], bfr[nt]);
        }
        if (kt + 1 < NKT) {
            const int nxt = ((kt + 1) & 1) * 128;
            __syncthreads();
            #pragma unroll
            for (int it = 0; it < 4; it++) {
                int row = nxt + l_row + it * 32;
                uint4 u; u.x = f2tf(pa[it].x); u.y = f2tf(pa[it].y); u.z = f2tf(pa[it].z); u.w = f2tf(pa[it].w);
                *(uint4*)&As[row][l_f] = u;
                uint4 v; v.x = f2tf(pb[it].x); v.y = f2tf(pb[it].y); v.z = f2tf(pb[it].z); v.w = f2tf(pb[it].w);
                *(uint4*)&Bs[row][l_f] = v;
            }
            __syncthreads();
        }
    }

    // epilogue
    #pragma unroll
    for (int mt = 0; mt < 2; mt++) {
        #pragma unroll
        for (int rh = 0; rh < 2; rh++) {
            int m = m0 + warp_m * 32 + mt * 16 + lq + rh * 8;
            int bb = m >> 11, sp = m & (S_ - 1);
            #pragma unroll
            for (int nt = 0; nt < 8; nt++) {
                int n = n0 + warp_n * 64 + nt * 8 + lr * 2;
                float2 b2 = *(const float2*)(bias + n);
                float v0 = c[mt][nt][rh * 2]     + b2.x;
                float v1 = c[mt][nt][rh * 2 + 1] + b2.y;
                if (MODE == 0) {
                    *(float2*)(out + (size_t)m * E_ + n) = make_float2(v0, v1);
                } else {
                    int h = n >> 6, d = n & 63;
                    float o0 = v0, o1 = v1;
                    if (MODE == 1) {
                        float2 cs = *(const float2*)(g_cos + sp * D_ + d);
                        float2 sn = *(const float2*)(g_sin + sp * D_ + d);
                        o0 = v0 * cs.x - v1 * sn.x;
                        o1 = v1 * cs.y + v0 * sn.y;
                    }
                    size_t base = (((size_t)(bb * H_ + h)) * S_ + sp) * D_ + d;
                    *(float2*)(out + base) = make_float2(o0, o1);
                }
            }
        }
    }
}

// ---------------------------------------------------------------------------
// Flash attention, tf32 mma + ldmatrix. 128 threads (4 warps), Q tile 64.
// Q frags in regs (pre-scaled 1/8). Qs smem reused as Ps.
// ---------------------------------------------------------------------------
__global__ __launch_bounds__(128) void attn_tc(float* __restrict__ outbuf)
{
    extern __shared__ unsigned smu[];
    unsigned (*Ks)[68] = (unsigned(*)[68])smu;
    unsigned (*Vs)[68] = (unsigned(*)[68])(smu + 64*68);
    unsigned (*Ps)[68] = (unsigned(*)[68])(smu + 2*64*68);  // also Q staging

    const int tid = threadIdx.x;
    const int lane = tid & 31, wid = tid >> 5;
    const int lq = lane >> 2, lr = lane & 3;
    const int wr = wid * 16;
    const int q0 = blockIdx.x * 64;
    const int h = blockIdx.y, bb = blockIdx.z;
    const size_t head_base = ((size_t)(bb * H_ + h)) * S_ * D_;

    const int a_ro = (lane & 7) + ((lane >> 3) & 1) * 8;
    const int a_co = ((lane >> 4) & 1) * 4;
    const int b_ro = (lane & 7) + ((lane >> 4) & 1) * 8;
    const int b_co = ((lane >> 3) & 1) * 4;

    const unsigned ks_u = smem_u32(&Ks[0][0]);
    const unsigned ps_u = smem_u32(&Ps[0][0]);

    // stage Q tile (64x64, scaled by 1/8) into Ps, extract fragments via ldsm
    #pragma unroll
    for (int it = 0; it < 8; it++) {
        int id = tid + it * 128;
        int row = id >> 4, f = (id & 15) * 4;
        float4 v = *(const float4*)(g_q + head_base + (size_t)(q0 + row) * D_ + f);
        uint4 u;
        u.x = f2tf(v.x * 0.125f); u.y = f2tf(v.y * 0.125f);
        u.z = f2tf(v.z * 0.125f); u.w = f2tf(v.w * 0.125f);
        *(uint4*)&Ps[row][f] = u;
    }
    __syncthreads();

    const unsigned pa_base = ps_u + (((wr + a_ro) * 68) + a_co) * 4u;
    unsigned qfr[8][4];
    #pragma unroll
    for (int kk = 0; kk < 8; kk++)
        ldsm4(qfr[kk][0], qfr[kk][1], qfr[kk][2], qfr[kk][3], pa_base + (kk * 8) * 4u);
    // Ps rows [wr, wr+16) are warp-private from here on.

    float o[8][4];
    float m_i[2] = {-1e30f, -1e30f}, l_i[2] = {0.f, 0.f};
    #pragma unroll
    for (int nt = 0; nt < 8; nt++)
        #pragma unroll
        for (int i = 0; i < 4; i++) o[nt][i] = 0.f;

    for (int kt = 0; kt < S_; kt += 64) {
        __syncthreads();   // previous iteration done reading Ks/Vs
        #pragma unroll
        for (int it = 0; it < 8; it++) {
            int id = tid + it * 128;
            int row = id >> 4, f = (id & 15) * 4;
            float4 kv = *(const float4*)(g_k + head_base + (size_t)(kt + row) * D_ + f);
            uint4 u;
            u.x = f2tf(kv.x); u.y = f2tf(kv.y); u.z = f2tf(kv.z); u.w = f2tf(kv.w);
            *(uint4*)&Ks[row][f] = u;
            float4 vv = *(const float4*)(g_v + head_base + (size_t)(kt + row) * D_ + f);
            uint4 w;
            w.x = f2tf(vv.x); w.y = f2tf(vv.y); w.z = f2tf(vv.z); w.w = f2tf(vv.w);
            *(uint4*)&Vs[row][f] = w;
        }
        __syncthreads();

        // S = (Q/8) K^T  — K B-frags via ldsm (4 x4-loads per kk)
        float s[8][4];
        #pragma unroll
        for (int nt = 0; nt < 8; nt++)
            #pragma unroll
            for (int i = 0; i < 4; i++) s[nt][i] = 0.f;

        const unsigned kb_base = ks_u + ((b_ro * 68) + b_co) * 4u;
        #pragma unroll
        for (int kk = 0; kk < 8; kk++) {
            int koff = kk * 8;
            unsigned bfr[8][2];
            #pragma unroll
            for (int p = 0; p < 4; p++) {
                unsigned r0, r1, r2, r3;
                ldsm4(r0, r1, r2, r3, kb_base + (p * 16 * 68 + koff) * 4u);
                bfr[2*p][0] = r0; bfr[2*p][1] = r1;
                bfr[2*p+1][0] = r2; bfr[2*p+1][1] = r3;
            }
            #pragma unroll
            for (int nt = 0; nt < 8; nt++)
                mma_tf32(s[nt], qfr[kk], bfr[nt]);
        }

        // online softmax (rows: lq -> c0/c1, lq+8 -> c2/c3)
        #pragma unroll
        for (int rh = 0; rh < 2; rh++) {
            float mx = -1e30f;
            #pragma unroll
            for (int nt = 0; nt < 8; nt++)
                mx = fmaxf(mx, fmaxf(s[nt][rh*2], s[nt][rh*2+1]));
            mx = fmaxf(mx, __shfl_xor_sync(0xffffffffu, mx, 1));
            mx = fmaxf(mx, __shfl_xor_sync(0xffffffffu, mx, 2));
            float mnew = fmaxf(m_i[rh], mx);
            float corr = __expf(m_i[rh] - mnew);
            m_i[rh] = mnew;
            float sum = 0.f;
            #pragma unroll
            for (int nt = 0; nt < 8; nt++) {
                float p0 = __expf(s[nt][rh*2]   - mnew);
                float p1 = __expf(s[nt][rh*2+1] - mnew);
                s[nt][rh*2] = p0; s[nt][rh*2+1] = p1;
                sum += p0 + p1;
            }
            sum += __shfl_xor_sync(0xffffffffu, sum, 1);
            sum += __shfl_xor_sync(0xffffffffu, sum, 2);
            l_i[rh] = l_i[rh] * corr + sum;
            #pragma unroll
            for (int nt = 0; nt < 8; nt++) {
                o[nt][rh*2]   *= corr;
                o[nt][rh*2+1] *= corr;
            }
        }

        // P -> smem (warp-private rows)
        #pragma unroll
        for (int nt = 0; nt < 8; nt++) {
            int col = nt * 8 + lr * 2;
            *(uint2*)&Ps[wr + lq][col]     = make_uint2(f2tf(s[nt][0]), f2tf(s[nt][1]));
            *(uint2*)&Ps[wr + lq + 8][col] = make_uint2(f2tf(s[nt][2]), f2tf(s[nt][3]));
        }
        __syncwarp();

        // O += P V  — P A-frags via ldsm, V B-frags scalar (k-major layout)
        #pragma unroll
        for (int kk = 0; kk < 8; kk++) {
            int koff = kk * 8;
            unsigned afr[4];
            ldsm4(afr[0], afr[1], afr[2], afr[3], pa_base + koff * 4u);
            #pragma unroll
            for (int nt = 0; nt < 8; nt++) {
                unsigned bfr[2];
                bfr[0] = Vs[koff + lr][nt * 8 + lq];
                bfr[1] = Vs[koff + 4 + lr][nt * 8 + lq];
                mma_tf32(o[nt], afr, bfr);
            }
        }
    }

    // normalize + write [B,S,H,D]
    float inv0 = 1.0f / l_i[0], inv1 = 1.0f / l_i[1];
    #pragma unroll
    for (int nt = 0; nt < 8; nt++) {
        int d = nt * 8 + lr * 2;
        size_t i0 = (((size_t)bb * S_ + q0 + wr + lq) * H_ + h) * D_ + d;
        size_t i1 = (((size_t)bb * S_ + q0 + wr + lq + 8) * H_ + h) * D_ + d;
        *(float2*)(outbuf + i0) = make_float2(o[nt][0] * inv0, o[nt][1] * inv0);
        *(float2*)(outbuf + i1) = make_float2(o[nt][2] * inv1, o[nt][3] * inv1);
    }
}

// ---------------------------------------------------------------------------
extern "C" void kernel_launch(void* const* d_in, const int* in_sizes, int n_in,
                              void* d_out, int out_size)
{
    const float* x  = (const float*)d_in[0];
    const float* Wq = (const float*)d_in[1];
    const float* bq = (const float*)d_in[2];
    const float* Wk = (const float*)d_in[3];
    const float* bk = (const float*)d_in[4];
    const float* Wv = (const float*)d_in[5];
    const float* bv = (const float*)d_in[6];
    const float* Wo = (const float*)d_in[7];
    const float* bo = (const float*)d_in[8];
    float* out = (float*)d_out;

    float *pq, *pk, *pv, *pa;
    cudaGetSymbolAddress((void**)&pq, g_q);
    cudaGetSymbolAddress((void**)&pk, g_k);
    cudaGetSymbolAddress((void**)&pv, g_v);
    cudaGetSymbolAddress((void**)&pa, g_attn);

    const int smem_gemm = 2 * 2 * 128 * 36 * sizeof(unsigned);  // 73728
    const int smem_attn = 3 * 64 * 68 * sizeof(unsigned);       // 52224
    cudaFuncSetAttribute(gemm_tc<0>, cudaFuncAttributeMaxDynamicSharedMemorySize, smem_gemm);
    cudaFuncSetAttribute(gemm_tc<1>, cudaFuncAttributeMaxDynamicSharedMemorySize, smem_gemm);
    cudaFuncSetAttribute(gemm_tc<2>, cudaFuncAttributeMaxDynamicSharedMemorySize, smem_gemm);
    cudaFuncSetAttribute(attn_tc,    cudaFuncAttributeMaxDynamicSharedMemorySize, smem_attn);

    rope_table_kernel<<<(S_*D_ + 255)/256, 256>>>();

    dim3 gg(E_/128, M_/128);   // (8, 32)
    gemm_tc<1><<<gg, 256, smem_gemm>>>(x,  Wq, bq, pq);
    gemm_tc<1><<<gg, 256, smem_gemm>>>(x,  Wk, bk, pk);
    gemm_tc<2><<<gg, 256, smem_gemm>>>(x,  Wv, bv, pv);
    attn_tc<<<dim3(S_/64, H_, B_), 128, smem_attn>>>(pa);
    gemm_tc<0><<<gg, 256, smem_gemm>>>(pa, Wo, bo, out);
}